// round 7
// baseline (speedup 1.0000x reference)
#include <cuda_runtime.h>

#define NVOX   262144
#define NU     65536
#define C_IN   128
#define C_HID  64
#define K_OUT  20
#define TILE   128
#define NTILES (NVOX / TILE)
#define HSV    130           // hs row stride, [j][v]
#define THREADS 512

typedef unsigned long long u64;

__device__ __forceinline__ u64 bcast2(float a) {
    u64 r; asm("mov.b64 %0, {%1, %1};" : "=l"(r) : "f"(a)); return r;
}
__device__ __forceinline__ u64 pack2(float a, float b) {
    u64 r; asm("mov.b64 %0, {%1, %2};" : "=l"(r) : "f"(a), "f"(b)); return r;
}
__device__ __forceinline__ void fma2(u64& d, u64 a, u64 b) {
    asm("fma.rn.f32x2 %0, %1, %2, %0;" : "+l"(d) : "l"(a), "l"(b));
}
__device__ __forceinline__ float2 unpk(u64 v) {
    float2 r; asm("mov.b64 {%0, %1}, %2;" : "=f"(r.x), "=f"(r.y) : "l"(v)); return r;
}
__device__ __forceinline__ float leaky(float x) {
    return fmaxf(x, 0.f) + 0.01f * fminf(x, 0.f);
}

__device__ int   g_rank[NVOX];
__device__ float g_W23[C_HID * C_HID];
__device__ float g_b23[C_HID];

__global__ void rank_kernel(const int* __restrict__ ui, const int* __restrict__ mi) {
    int t = blockIdx.x * blockDim.x + threadIdx.x;
    if (t < NU)        g_rank[ui[t]]      = t;
    else if (t < NVOX) g_rank[mi[t - NU]] = -1;
}

// W23 = w2 @ sdb_w  [64j x 64j2], b23 = b2 @ sdb_w + sdb_b
__global__ void w23_kernel(const float* __restrict__ w2, const float* __restrict__ sdb_w,
                           const float* __restrict__ b2, const float* __restrict__ sdb_b) {
    int idx = blockIdx.x * blockDim.x + threadIdx.x;     // 16 x 256 = 4096
    if (idx < C_HID * C_HID) {
        int j = idx >> 6, j2 = idx & 63;
        float acc = 0.f;
        #pragma unroll 8
        for (int c = 0; c < C_IN; ++c)
            acc += w2[j * C_IN + c] * sdb_w[c * C_HID + j2];
        g_W23[idx] = acc;
    }
    if (idx < C_HID) {
        float acc = sdb_b[idx];
        #pragma unroll 8
        for (int c = 0; c < C_IN; ++c)
            acc += b2[c] * sdb_w[c * C_HID + idx];
        g_b23[idx] = acc;
    }
}

struct __align__(16) Smem {
    float fs[C_IN * TILE];        // [c][v] feats (read-only after load)
    float hs[C_HID * HSV];        // [j][v] raw h (GEMM1), then d
    float w1s [C_IN * C_HID];     // [c][j]
    float sdbs[C_IN * C_HID];     // [c][j2]
    float W23s[C_HID * C_HID];    // [j][j2]
    float sscs[C_HID * K_OUT];    // [j2][k]
    float auxs[C_IN * K_OUT];     // [c][k]
    float b1s[C_HID], lngs[C_HID], lnbs[C_HID], sdbbs[C_HID], b23s[C_HID];
    float sscbs[K_OUT], auxbs[K_OUT];
    float mus[TILE], rss[TILE];
    float red1[4 * TILE], red2[4 * TILE];
    int   ranks[TILE];
    int   lstv[TILE], lstr[TILE];
    int   cnt, pad[3];
};

__global__ void __launch_bounds__(THREADS, 1)
fused_kernel(const float* __restrict__ x3d,
             const float* __restrict__ w1,    const float* __restrict__ b1,
             const float* __restrict__ ln_g,  const float* __restrict__ ln_b,
             const float* __restrict__ sdb_w, const float* __restrict__ sdb_b,
             const float* __restrict__ ssc_w, const float* __restrict__ ssc_b,
             const float* __restrict__ aux_w, const float* __restrict__ aux_b,
             float* __restrict__ out)
{
    extern __shared__ char smem_raw[];
    Smem* s = reinterpret_cast<Smem*>(smem_raw);
    const int t = threadIdx.x;
    const int warp = t >> 5, lane = t & 31;

    for (int i = t; i < C_IN * C_HID;   i += THREADS) s->w1s[i]  = w1[i];
    for (int i = t; i < C_IN * C_HID;   i += THREADS) s->sdbs[i] = sdb_w[i];
    for (int i = t; i < C_HID * C_HID;  i += THREADS) s->W23s[i] = g_W23[i];
    for (int i = t; i < C_HID * K_OUT;  i += THREADS) s->sscs[i] = ssc_w[i];
    for (int i = t; i < C_IN * K_OUT;   i += THREADS) s->auxs[i] = aux_w[i];
    if (t < C_HID) {
        s->b1s[t] = b1[t]; s->lngs[t] = ln_g[t]; s->lnbs[t] = ln_b[t];
        s->sdbbs[t] = sdb_b[t]; s->b23s[t] = g_b23[t];
    }
    if (t < K_OUT) { s->sscbs[t] = ssc_b[t]; s->auxbs[t] = aux_b[t]; }

    float* outsem = out + (size_t)K_OUT * NVOX;

    // GEMM1 mapping: warp = 16 v-pairs x 2 j-blocks; thread = 2v x 8j
    const int vp1   = (warp & 3) * 16 + (lane & 15);
    const int jblk1 = (warp >> 2) * 2 + (lane >> 4);
    // pass A mapping: thread = v-pair (t&63) x 8 j2 (t>>6)
    const int pA  = t & 63;
    const int jbA = t >> 6;

    for (int tile = blockIdx.x; tile < NTILES; tile += gridDim.x) {
        const int vbase = tile * TILE;
        __syncthreads();
        if (t == 0) s->cnt = 0;

        // ---- load feats tile [128 c][128 v] ----
        #pragma unroll
        for (int it = 0; it < 8; ++it) {
            int i  = t + it * THREADS;
            int c  = i >> 5;
            int vq = i & 31;
            *reinterpret_cast<float4*>(&s->fs[c * TILE + vq * 4]) =
                *reinterpret_cast<const float4*>(&x3d[(size_t)c * NVOX + vbase + vq * 4]);
        }
        if (t < TILE) s->ranks[t] = g_rank[vbase + t];
        __syncthreads();
        if (t < TILE) {
            int r = s->ranks[t];
            if (r >= 0) { int p = atomicAdd(&s->cnt, 1); s->lstv[p] = t; s->lstr[p] = r; }
        }

        // ---- GEMM1: raw h = feats @ w1 + b1 -> hs[j][v] ----
        {
            const int v0 = vp1 * 2, j0 = jblk1 * 8;
            u64 acc[2][4];
            {
                const u64* bp = reinterpret_cast<const u64*>(s->b1s + j0);
                #pragma unroll
                for (int jp = 0; jp < 4; ++jp) { acc[0][jp] = bp[jp]; acc[1][jp] = bp[jp]; }
            }
            const float* fp = s->fs + v0;
            const float* wp = s->w1s + j0;
            #pragma unroll 4
            for (int c = 0; c < C_IN; ++c) {
                float2 f = *reinterpret_cast<const float2*>(fp + c * TILE);
                u64 d0 = bcast2(f.x), d1 = bcast2(f.y);
                ulonglong2 wa = *reinterpret_cast<const ulonglong2*>(wp + c * C_HID);
                ulonglong2 wb = *reinterpret_cast<const ulonglong2*>(wp + c * C_HID + 4);
                fma2(acc[0][0], d0, wa.x); fma2(acc[1][0], d1, wa.x);
                fma2(acc[0][1], d0, wa.y); fma2(acc[1][1], d1, wa.y);
                fma2(acc[0][2], d0, wb.x); fma2(acc[1][2], d1, wb.x);
                fma2(acc[0][3], d0, wb.y); fma2(acc[1][3], d1, wb.y);
            }
            #pragma unroll
            for (int jp = 0; jp < 4; ++jp) {
                float2 q0 = unpk(acc[0][jp]);   // (j0+2jp, j0+2jp+1) for v0
                float2 q1 = unpk(acc[1][jp]);   // for v0+1
                *reinterpret_cast<u64*>(&s->hs[(j0 + 2*jp)     * HSV + v0]) = pack2(q0.x, q1.x);
                *reinterpret_cast<u64*>(&s->hs[(j0 + 2*jp + 1) * HSV + v0]) = pack2(q0.y, q1.y);
            }
        }
        __syncthreads();

        // ---- LayerNorm stats ----
        {
            int v = t & 127, q = t >> 7;
            float sum = 0.f, ssum = 0.f;
            #pragma unroll 8
            for (int jj = 0; jj < 16; ++jj) {
                float x = s->hs[(q * 16 + jj) * HSV + v];
                sum += x; ssum += x * x;
            }
            s->red1[q * TILE + v] = sum;
            s->red2[q * TILE + v] = ssum;
        }
        __syncthreads();
        if (t < TILE) {
            float sum  = s->red1[t] + s->red1[TILE + t] + s->red1[2*TILE + t] + s->red1[3*TILE + t];
            float ssum = s->red2[t] + s->red2[TILE + t] + s->red2[2*TILE + t] + s->red2[3*TILE + t];
            float mu  = sum * (1.f / 64.f);
            float var = ssum * (1.f / 64.f) - mu * mu;
            s->mus[t] = mu;
            s->rss[t] = rsqrtf(var + 1e-5f);
        }
        __syncthreads();

        // ---- pass A: d = leaky( leaky(LN(h)) @ W23 + b23 ), K=64; LN fused into reads ----
        {
            const int v0 = pA * 2, j20 = jbA * 8;
            const float mu0 = s->mus[v0],     rs0 = s->rss[v0];
            const float mu1 = s->mus[v0 + 1], rs1 = s->rss[v0 + 1];
            u64 acc[2][4];
            {
                const u64* bp = reinterpret_cast<const u64*>(s->b23s + j20);
                #pragma unroll
                for (int jp = 0; jp < 4; ++jp) { acc[0][jp] = bp[jp]; acc[1][jp] = bp[jp]; }
            }
            #pragma unroll 4
            for (int j = 0; j < C_HID; ++j) {
                float2 f = *reinterpret_cast<const float2*>(&s->hs[j * HSV + v0]);
                float g = s->lngs[j], bb = s->lnbs[j];
                float x0 = leaky((f.x - mu0) * rs0 * g + bb);
                float x1 = leaky((f.y - mu1) * rs1 * g + bb);
                u64 d0 = bcast2(x0), d1 = bcast2(x1);
                ulonglong2 wa = *reinterpret_cast<const ulonglong2*>(&s->W23s[j * C_HID + j20]);
                ulonglong2 wb = *reinterpret_cast<const ulonglong2*>(&s->W23s[j * C_HID + j20 + 4]);
                fma2(acc[0][0], d0, wa.x); fma2(acc[1][0], d1, wa.x);
                fma2(acc[0][1], d0, wa.y); fma2(acc[1][1], d1, wa.y);
                fma2(acc[0][2], d0, wb.x); fma2(acc[1][2], d1, wb.x);
                fma2(acc[0][3], d0, wb.y); fma2(acc[1][3], d1, wb.y);
            }
            __syncthreads();                   // all h reads complete
            #pragma unroll
            for (int jp = 0; jp < 4; ++jp) {
                float2 q0 = unpk(acc[0][jp]);
                float2 q1 = unpk(acc[1][jp]);
                int j2 = j20 + 2 * jp;
                *reinterpret_cast<u64*>(&s->hs[j2       * HSV + v0]) = pack2(leaky(q0.x), leaky(q1.x));
                *reinterpret_cast<u64*>(&s->hs[(j2 + 1) * HSV + v0]) = pack2(leaky(q0.y), leaky(q1.y));
            }
        }
        __syncthreads();

        // ---- pass B: unmasked voxels only: d = leaky(feats @ sdb_w + sdb_b), K=128 ----
        {
            const int nu = s->cnt;
            for (int i = t; i < nu * 8; i += THREADS) {
                int u = i >> 3, jb = i & 7;
                int v = s->lstv[u];
                const int j20 = jb * 8;
                u64 acc[4];
                {
                    const u64* bp = reinterpret_cast<const u64*>(s->sdbbs + j20);
                    #pragma unroll
                    for (int jp = 0; jp < 4; ++jp) acc[jp] = bp[jp];
                }
                const float* fcol = &s->fs[v];
                const float* wp = s->sdbs + j20;
                #pragma unroll 4
                for (int c = 0; c < C_IN; ++c) {
                    u64 fb = bcast2(fcol[c * TILE]);
                    ulonglong2 wa = *reinterpret_cast<const ulonglong2*>(wp + c * C_HID);
                    ulonglong2 wb = *reinterpret_cast<const ulonglong2*>(wp + c * C_HID + 4);
                    fma2(acc[0], fb, wa.x);
                    fma2(acc[1], fb, wa.y);
                    fma2(acc[2], fb, wb.x);
                    fma2(acc[3], fb, wb.y);
                }
                #pragma unroll
                for (int jp = 0; jp < 4; ++jp) {
                    float2 q = unpk(acc[jp]);
                    int j2 = j20 + 2 * jp;
                    s->hs[j2       * HSV + v] = leaky(q.x);
                    s->hs[(j2 + 1) * HSV + v] = leaky(q.y);
                }
            }
        }
        __syncthreads();

        // ---- heads: warps 0-9 SSC (k-pair each), warps 10-15 AUX ----
        if (warp < 10) {
            const int k0 = warp * 2;
            u64 acc[4];
            {
                u64 b = pack2(s->sscbs[k0], s->sscbs[k0 + 1]);
                #pragma unroll
                for (int q = 0; q < 4; ++q) acc[q] = b;
            }
            const float* hp = &s->hs[lane];
            const float* wp = &s->sscs[k0];
            #pragma unroll 4
            for (int j = 0; j < C_HID; ++j) {
                u64 wpair = *reinterpret_cast<const u64*>(wp + j * K_OUT);
                fma2(acc[0], bcast2(hp[j * HSV]),      wpair);
                fma2(acc[1], bcast2(hp[j * HSV + 32]), wpair);
                fma2(acc[2], bcast2(hp[j * HSV + 64]), wpair);
                fma2(acc[3], bcast2(hp[j * HSV + 96]), wpair);
            }
            float* o0 = &out[(size_t)k0 * NVOX + vbase];
            float* o1 = &out[(size_t)(k0 + 1) * NVOX + vbase];
            #pragma unroll
            for (int q = 0; q < 4; ++q) {
                float2 pr = unpk(acc[q]);
                o0[lane + 32 * q] = pr.x;
                o1[lane + 32 * q] = pr.y;
            }
        } else {
            const int nu = s->cnt;
            for (int i = lane + (warp - 10) * 32; i < nu; i += 192) {
                int v = s->lstv[i], r = s->lstr[i];
                u64 acc[10];
                const u64* bb = reinterpret_cast<const u64*>(s->auxbs);
                #pragma unroll
                for (int kp = 0; kp < 10; ++kp) acc[kp] = bb[kp];
                const float* fcol = &s->fs[v];
                #pragma unroll 4
                for (int c = 0; c < C_IN; ++c) {
                    u64 fb = bcast2(fcol[c * TILE]);
                    const u64* wr = reinterpret_cast<const u64*>(&s->auxs[c * K_OUT]);
                    #pragma unroll
                    for (int kp = 0; kp < 10; ++kp) fma2(acc[kp], fb, wr[kp]);
                }
                u64* orow = reinterpret_cast<u64*>(&outsem[(size_t)r * K_OUT]);
                #pragma unroll
                for (int kp = 0; kp < 10; ++kp) orow[kp] = acc[kp];
            }
        }
    }
}

extern "C" void kernel_launch(void* const* d_in, const int* in_sizes, int n_in,
                              void* d_out, int out_size)
{
    const float* x3d   = (const float*)d_in[0];
    const float* w1    = (const float*)d_in[1];
    const float* b1    = (const float*)d_in[2];
    const float* ln_g  = (const float*)d_in[3];
    const float* ln_b  = (const float*)d_in[4];
    const float* w2    = (const float*)d_in[5];
    const float* b2    = (const float*)d_in[6];
    const float* sdb_w = (const float*)d_in[7];
    const float* sdb_b = (const float*)d_in[8];
    const float* ssc_w = (const float*)d_in[9];
    const float* ssc_b = (const float*)d_in[10];
    const float* aux_w = (const float*)d_in[11];
    const float* aux_b = (const float*)d_in[12];
    const int* ui      = (const int*)d_in[13];
    const int* mi      = (const int*)d_in[14];
    float* out         = (float*)d_out;

    int nsm = 0;
    cudaDeviceGetAttribute(&nsm, cudaDevAttrMultiProcessorCount, 0);
    if (nsm <= 0) nsm = 148;

    cudaFuncSetAttribute(fused_kernel,
                         cudaFuncAttributeMaxDynamicSharedMemorySize,
                         (int)sizeof(Smem));

    rank_kernel<<<NVOX / 256, 256>>>(ui, mi);
    w23_kernel<<<16, 256>>>(w2, sdb_w, b2, sdb_b);
    fused_kernel<<<nsm, THREADS, sizeof(Smem)>>>(x3d, w1, b1, ln_g, ln_b,
                                                 sdb_w, sdb_b, ssc_w, ssc_b,
                                                 aux_w, aux_b, out);
}

// round 8
// speedup vs baseline: 1.1722x; 1.1722x over previous
#include <cuda_runtime.h>

#define NVOX   262144
#define NU     65536
#define C_IN   128
#define C_HID  64
#define K_OUT  20
#define TILE   128
#define NTILES (NVOX / TILE)
#define HSV    130           // hs row stride, [j][v]
#define THREADS 512

typedef unsigned long long u64;

__device__ __forceinline__ u64 bcast2(float a) {
    u64 r; asm("mov.b64 %0, {%1, %1};" : "=l"(r) : "f"(a)); return r;
}
__device__ __forceinline__ u64 pack2(float a, float b) {
    u64 r; asm("mov.b64 %0, {%1, %2};" : "=l"(r) : "f"(a), "f"(b)); return r;
}
__device__ __forceinline__ void fma2(u64& d, u64 a, u64 b) {
    asm("fma.rn.f32x2 %0, %1, %2, %0;" : "+l"(d) : "l"(a), "l"(b));
}
__device__ __forceinline__ float2 unpk(u64 v) {
    float2 r; asm("mov.b64 {%0, %1}, %2;" : "=f"(r.x), "=f"(r.y) : "l"(v)); return r;
}
__device__ __forceinline__ float leaky(float x) {
    return fmaxf(x, 0.f) + 0.01f * fminf(x, 0.f);
}

__device__ int   g_rank[NVOX];
__device__ float g_W23[C_HID * C_HID];
__device__ float g_b23[C_HID];

__global__ void rank_kernel(const int* __restrict__ ui, const int* __restrict__ mi) {
    int t = blockIdx.x * blockDim.x + threadIdx.x;
    if (t < NU)        g_rank[ui[t]]      = t;
    else if (t < NVOX) g_rank[mi[t - NU]] = -1;
}

// W23 = w2 @ sdb_w  [64j x 64j2], b23 = b2 @ sdb_w + sdb_b
__global__ void w23_kernel(const float* __restrict__ w2, const float* __restrict__ sdb_w,
                           const float* __restrict__ b2, const float* __restrict__ sdb_b) {
    int idx = blockIdx.x * blockDim.x + threadIdx.x;
    if (idx < C_HID * C_HID) {
        int j = idx >> 6, j2 = idx & 63;
        float acc = 0.f;
        #pragma unroll 8
        for (int c = 0; c < C_IN; ++c)
            acc += w2[j * C_IN + c] * sdb_w[c * C_HID + j2];
        g_W23[idx] = acc;
    }
    if (idx < C_HID) {
        float acc = sdb_b[idx];
        #pragma unroll 8
        for (int c = 0; c < C_IN; ++c)
            acc += b2[c] * sdb_w[c * C_HID + idx];
        g_b23[idx] = acc;
    }
}

struct __align__(16) Smem {
    float fs[C_IN * TILE];        // [c][v] feats, read-only after load
    float hs[C_HID * HSV];        // [j][v] raw h -> normalized h -> d
    float w1s [C_IN * C_HID];     // [c][j]
    float sdbs[C_IN * C_HID];     // [c][j2]
    float W23s[C_HID * C_HID];    // [j][j2]
    float sscs[C_HID * K_OUT];    // [j2][k]
    float auxs[C_IN * K_OUT];     // [c][k]
    float b1s[C_HID], lngs[C_HID], lnbs[C_HID], sdbbs[C_HID], b23s[C_HID];
    float sscbs[K_OUT], auxbs[K_OUT];
    float mus[TILE], rss[TILE];
    float red1[4 * TILE], red2[4 * TILE];
    int   ranks[TILE];
    int   lstv[TILE], lstr[TILE];
    int   cnt, pad[3];
};

__global__ void __launch_bounds__(THREADS, 1)
fused_kernel(const float* __restrict__ x3d,
             const float* __restrict__ w1,    const float* __restrict__ b1,
             const float* __restrict__ ln_g,  const float* __restrict__ ln_b,
             const float* __restrict__ sdb_w, const float* __restrict__ sdb_b,
             const float* __restrict__ ssc_w, const float* __restrict__ ssc_b,
             const float* __restrict__ aux_w, const float* __restrict__ aux_b,
             float* __restrict__ out)
{
    extern __shared__ char smem_raw[];
    Smem* s = reinterpret_cast<Smem*>(smem_raw);
    const int t = threadIdx.x;
    const int warp = t >> 5, lane = t & 31;

    for (int i = t; i < C_IN * C_HID;   i += THREADS) s->w1s[i]  = w1[i];
    for (int i = t; i < C_IN * C_HID;   i += THREADS) s->sdbs[i] = sdb_w[i];
    for (int i = t; i < C_HID * C_HID;  i += THREADS) s->W23s[i] = g_W23[i];
    for (int i = t; i < C_HID * K_OUT;  i += THREADS) s->sscs[i] = ssc_w[i];
    for (int i = t; i < C_IN * K_OUT;   i += THREADS) s->auxs[i] = aux_w[i];
    if (t < C_HID) {
        s->b1s[t] = b1[t]; s->lngs[t] = ln_g[t]; s->lnbs[t] = ln_b[t];
        s->sdbbs[t] = sdb_b[t]; s->b23s[t] = g_b23[t];
    }
    if (t < K_OUT) { s->sscbs[t] = ssc_b[t]; s->auxbs[t] = aux_b[t]; }

    float* outsem = out + (size_t)K_OUT * NVOX;

    // GEMM1: warp = 1 j-block x 32 v-pairs (w loads warp-uniform)
    const int jb1 = warp & 7, vh1 = warp >> 3;
    const int v0g = (vh1 * 32 + lane) * 2;
    const int j0g = jb1 * 8;
    // pass A: thread = v-pair (t&63) x 8 j2 (t>>6); W23 loads warp-uniform
    const int v0A = (t & 63) * 2;
    const int j2A = (t >> 6) * 8;

    for (int tile = blockIdx.x; tile < NTILES; tile += gridDim.x) {
        const int vbase = tile * TILE;
        __syncthreads();
        if (t == 0) s->cnt = 0;

        // ---- load feats tile [128 c][128 v] ----
        #pragma unroll
        for (int it = 0; it < 8; ++it) {
            int i  = t + it * THREADS;
            int c  = i >> 5;
            int vq = i & 31;
            *reinterpret_cast<float4*>(&s->fs[c * TILE + vq * 4]) =
                *reinterpret_cast<const float4*>(&x3d[(size_t)c * NVOX + vbase + vq * 4]);
        }
        if (t < TILE) s->ranks[t] = g_rank[vbase + t];
        __syncthreads();
        if (t < TILE) {
            int r = s->ranks[t];
            if (r >= 0) { int p = atomicAdd(&s->cnt, 1); s->lstv[p] = t; s->lstr[p] = r; }
        }

        // ---- GEMM1: raw h = feats @ w1 + b1 -> hs[j][v] ----
        {
            u64 acc[2][4];    // [vv][j-pair]
            {
                const u64* bp = reinterpret_cast<const u64*>(s->b1s + j0g);
                #pragma unroll
                for (int jp = 0; jp < 4; ++jp) { acc[0][jp] = bp[jp]; acc[1][jp] = bp[jp]; }
            }
            const float* fp = s->fs + v0g;
            const float* wp = s->w1s + j0g;
            #pragma unroll 4
            for (int c = 0; c < C_IN; ++c) {
                float2 f = *reinterpret_cast<const float2*>(fp + c * TILE);
                u64 d0 = bcast2(f.x), d1 = bcast2(f.y);
                ulonglong2 wa = *reinterpret_cast<const ulonglong2*>(wp + c * C_HID);
                ulonglong2 wb = *reinterpret_cast<const ulonglong2*>(wp + c * C_HID + 4);
                fma2(acc[0][0], d0, wa.x); fma2(acc[1][0], d1, wa.x);
                fma2(acc[0][1], d0, wa.y); fma2(acc[1][1], d1, wa.y);
                fma2(acc[0][2], d0, wb.x); fma2(acc[1][2], d1, wb.x);
                fma2(acc[0][3], d0, wb.y); fma2(acc[1][3], d1, wb.y);
            }
            #pragma unroll
            for (int jp = 0; jp < 4; ++jp) {
                float2 q0 = unpk(acc[0][jp]);   // (j0+2jp, j0+2jp+1) @ v0g
                float2 q1 = unpk(acc[1][jp]);   // @ v0g+1
                s->hs[(j0g + 2*jp)     * HSV + v0g]     = q0.x;
                s->hs[(j0g + 2*jp)     * HSV + v0g + 1] = q1.x;
                s->hs[(j0g + 2*jp + 1) * HSV + v0g]     = q0.y;
                s->hs[(j0g + 2*jp + 1) * HSV + v0g + 1] = q1.y;
            }
        }
        __syncthreads();

        // ---- LayerNorm stats (4 threads per voxel) ----
        {
            int v = t & 127, q = t >> 7;
            float sum = 0.f, ssum = 0.f;
            #pragma unroll 8
            for (int jj = 0; jj < 16; ++jj) {
                float x = s->hs[(q * 16 + jj) * HSV + v];
                sum += x; ssum += x * x;
            }
            s->red1[q * TILE + v] = sum;
            s->red2[q * TILE + v] = ssum;
        }
        __syncthreads();
        if (t < TILE) {
            float sum  = s->red1[t] + s->red1[TILE + t] + s->red1[2*TILE + t] + s->red1[3*TILE + t];
            float ssum = s->red2[t] + s->red2[TILE + t] + s->red2[2*TILE + t] + s->red2[3*TILE + t];
            float mu  = sum * (1.f / 64.f);
            float var = ssum * (1.f / 64.f) - mu * mu;
            s->mus[t] = mu;
            s->rss[t] = rsqrtf(var + 1e-5f);
        }
        __syncthreads();

        // ---- LN apply + leaky, u64 pairs (8 iterations) ----
        #pragma unroll
        for (int it = 0; it < 8; ++it) {
            int i = t + it * THREADS;          // 0..4095 v-pairs x j
            int j = i >> 6, vp = i & 63;
            int v0 = vp * 2;
            float g = s->lngs[j], bb = s->lnbs[j];
            u64 x2 = *reinterpret_cast<const u64*>(&s->hs[j * HSV + v0]);
            float2 x = unpk(x2);
            x.x = leaky((x.x - s->mus[v0])     * s->rss[v0]     * g + bb);
            x.y = leaky((x.y - s->mus[v0 + 1]) * s->rss[v0 + 1] * g + bb);
            *reinterpret_cast<u64*>(&s->hs[j * HSV + v0]) = pack2(x.x, x.y);
        }
        __syncthreads();

        // ---- pass A: d_masked = leaky(h_norm @ W23 + b23), K=64, in-place ----
        {
            u64 acc[2][4];
            {
                const u64* bp = reinterpret_cast<const u64*>(s->b23s + j2A);
                #pragma unroll
                for (int jp = 0; jp < 4; ++jp) { acc[0][jp] = bp[jp]; acc[1][jp] = bp[jp]; }
            }
            const float* hp = &s->hs[v0A];
            const float* wp = s->W23s + j2A;
            #pragma unroll 4
            for (int j = 0; j < C_HID; ++j) {
                float2 h2 = *reinterpret_cast<const float2*>(hp + j * HSV);
                u64 d0 = bcast2(h2.x), d1 = bcast2(h2.y);
                ulonglong2 wa = *reinterpret_cast<const ulonglong2*>(wp + j * C_HID);
                ulonglong2 wb = *reinterpret_cast<const ulonglong2*>(wp + j * C_HID + 4);
                fma2(acc[0][0], d0, wa.x); fma2(acc[1][0], d1, wa.x);
                fma2(acc[0][1], d0, wa.y); fma2(acc[1][1], d1, wa.y);
                fma2(acc[0][2], d0, wb.x); fma2(acc[1][2], d1, wb.x);
                fma2(acc[0][3], d0, wb.y); fma2(acc[1][3], d1, wb.y);
            }
            __syncthreads();                   // all reads of h complete
            #pragma unroll
            for (int jp = 0; jp < 4; ++jp) {
                float2 q0 = unpk(acc[0][jp]);
                float2 q1 = unpk(acc[1][jp]);
                s->hs[(j2A + 2*jp)     * HSV + v0A]     = leaky(q0.x);
                s->hs[(j2A + 2*jp)     * HSV + v0A + 1] = leaky(q1.x);
                s->hs[(j2A + 2*jp + 1) * HSV + v0A]     = leaky(q0.y);
                s->hs[(j2A + 2*jp + 1) * HSV + v0A + 1] = leaky(q1.y);
            }
        }
        __syncthreads();

        // ---- pass B: overwrite unmasked columns: d = leaky(feats @ sdb_w + sdb_b), K=128 ----
        {
            const int nu = s->cnt;
            for (int i = t; i < nu * 16; i += THREADS) {
                int u = i >> 4, qb = i & 15;
                int v = s->lstv[u];
                const int j20 = qb * 4;
                u64 a0, a1;
                {
                    const u64* bp = reinterpret_cast<const u64*>(s->sdbbs + j20);
                    a0 = bp[0]; a1 = bp[1];
                }
                const float* fcol = &s->fs[v];
                const float* wp = s->sdbs + j20;
                #pragma unroll 4
                for (int c = 0; c < C_IN; ++c) {
                    u64 fb = bcast2(fcol[c * TILE]);
                    ulonglong2 w = *reinterpret_cast<const ulonglong2*>(wp + c * C_HID);
                    fma2(a0, fb, w.x);
                    fma2(a1, fb, w.y);
                }
                float2 q0 = unpk(a0), q1 = unpk(a1);
                s->hs[(j20)     * HSV + v] = leaky(q0.x);
                s->hs[(j20 + 1) * HSV + v] = leaky(q0.y);
                s->hs[(j20 + 2) * HSV + v] = leaky(q1.x);
                s->hs[(j20 + 3) * HSV + v] = leaky(q1.y);
            }
        }
        __syncthreads();

        // ---- heads: warps 0-9 SSC (k-pair each), warps 10-15 AUX ----
        if (warp < 10) {
            const int k0 = warp * 2;
            u64 acc[4];
            {
                u64 b = pack2(s->sscbs[k0], s->sscbs[k0 + 1]);
                #pragma unroll
                for (int q = 0; q < 4; ++q) acc[q] = b;
            }
            const float* hp = &s->hs[lane];
            const float* wp = &s->sscs[k0];
            #pragma unroll 4
            for (int j = 0; j < C_HID; ++j) {
                u64 wpair = *reinterpret_cast<const u64*>(wp + j * K_OUT);
                fma2(acc[0], bcast2(hp[j * HSV]),      wpair);
                fma2(acc[1], bcast2(hp[j * HSV + 32]), wpair);
                fma2(acc[2], bcast2(hp[j * HSV + 64]), wpair);
                fma2(acc[3], bcast2(hp[j * HSV + 96]), wpair);
            }
            float* o0 = &out[(size_t)k0 * NVOX + vbase];
            float* o1 = &out[(size_t)(k0 + 1) * NVOX + vbase];
            #pragma unroll
            for (int q = 0; q < 4; ++q) {
                float2 pr = unpk(acc[q]);
                o0[lane + 32 * q] = pr.x;
                o1[lane + 32 * q] = pr.y;
            }
        } else {
            const int nu = s->cnt;
            for (int i = lane + (warp - 10) * 32; i < nu; i += 192) {
                int v = s->lstv[i], r = s->lstr[i];
                u64 acc[10];
                const u64* bb = reinterpret_cast<const u64*>(s->auxbs);
                #pragma unroll
                for (int kp = 0; kp < 10; ++kp) acc[kp] = bb[kp];
                const float* fcol = &s->fs[v];
                #pragma unroll 4
                for (int c = 0; c < C_IN; ++c) {
                    u64 fb = bcast2(fcol[c * TILE]);
                    const u64* wr = reinterpret_cast<const u64*>(&s->auxs[c * K_OUT]);
                    #pragma unroll
                    for (int kp = 0; kp < 10; ++kp) fma2(acc[kp], fb, wr[kp]);
                }
                u64* orow = reinterpret_cast<u64*>(&outsem[(size_t)r * K_OUT]);
                #pragma unroll
                for (int kp = 0; kp < 10; ++kp) orow[kp] = acc[kp];
            }
        }
    }
}

extern "C" void kernel_launch(void* const* d_in, const int* in_sizes, int n_in,
                              void* d_out, int out_size)
{
    const float* x3d   = (const float*)d_in[0];
    const float* w1    = (const float*)d_in[1];
    const float* b1    = (const float*)d_in[2];
    const float* ln_g  = (const float*)d_in[3];
    const float* ln_b  = (const float*)d_in[4];
    const float* w2    = (const float*)d_in[5];
    const float* b2    = (const float*)d_in[6];
    const float* sdb_w = (const float*)d_in[7];
    const float* sdb_b = (const float*)d_in[8];
    const float* ssc_w = (const float*)d_in[9];
    const float* ssc_b = (const float*)d_in[10];
    const float* aux_w = (const float*)d_in[11];
    const float* aux_b = (const float*)d_in[12];
    const int* ui      = (const int*)d_in[13];
    const int* mi      = (const int*)d_in[14];
    float* out         = (float*)d_out;

    int nsm = 0;
    cudaDeviceGetAttribute(&nsm, cudaDevAttrMultiProcessorCount, 0);
    if (nsm <= 0) nsm = 148;

    cudaFuncSetAttribute(fused_kernel,
                         cudaFuncAttributeMaxDynamicSharedMemorySize,
                         (int)sizeof(Smem));

    rank_kernel<<<NVOX / 256, 256>>>(ui, mi);
    w23_kernel<<<16, 256>>>(w2, sdb_w, b2, sdb_b);
    fused_kernel<<<nsm, THREADS, sizeof(Smem)>>>(x3d, w1, b1, ln_g, ln_b,
                                                 sdb_w, sdb_b, ssc_w, ssc_b,
                                                 aux_w, aux_b, out);
}